// round 14
// baseline (speedup 1.0000x reference)
#include <cuda_runtime.h>
#include <cuda_fp16.h>
#include <cstdint>

#define CIN    128
#define OUTC   128
#define T_IN   32768
#define P_OUT  32769
#define NTILE2 4104          // 513 p-tiles(64 pos) * 8 batches
#define GRID   456           // 3 CTAs per SM
#define NSTR   456           // one stream per CTA

#define WP 132               // u64 pitch of W image rows
#define XP 72                // f32 pitch, x rows (bank = 8t+g, conflict-free; 288B)
#define NSTAGE 5
#define LOOKAHEAD 3
#define CHUNK_B   (16 * XP * 4)      // 4608 B per chunk (16 channels x 72 f32)

// smem byte offsets (23680 B per CTA -> 3 CTAs/SM)
#define SM_X    0                    // 5 stages x 4608 = 23040
#define SM_BIAS 23040                // 512
#define SM_MBAR 23552                // 5 full + 5 empty x 8B = 80
#define SM_TOT  23680

typedef unsigned long long u64;

// W image: [pr][o] u64 = { lo32: f16x2 pair(kr=r), hi32: f16x2 pair(kr=r+4) }
__device__ __align__(16) u64 g_W64[64 * WP];

__device__ __forceinline__ uint32_t smem_u32(const void* p) {
    uint32_t a;
    asm("{ .reg .u64 t; cvta.to.shared.u64 t, %1; cvt.u32.u64 %0, t; }" : "=r"(a) : "l"(p));
    return a;
}
__device__ __forceinline__ uint32_t cvt2h(float hi, float lo) {
    uint32_t r;
    asm("cvt.rn.f16x2.f32 %0, %1, %2;" : "=r"(r) : "f"(hi), "f"(lo));
    return r;
}
__device__ __forceinline__ void mma16816h(float* d, const uint32_t* a, uint32_t b0, uint32_t b1) {
    asm volatile(
        "mma.sync.aligned.m16n8k16.row.col.f32.f16.f16.f32 "
        "{%0,%1,%2,%3}, {%4,%5,%6,%7}, {%8,%9}, {%0,%1,%2,%3};"
        : "+f"(d[0]), "+f"(d[1]), "+f"(d[2]), "+f"(d[3])
        : "r"(a[0]), "r"(a[1]), "r"(a[2]), "r"(a[3]), "r"(b0), "r"(b1));
}
__device__ __forceinline__ void mbar_init(uint32_t m, uint32_t cnt) {
    asm volatile("mbarrier.init.shared.b64 [%0], %1;" :: "r"(m), "r"(cnt) : "memory");
}
__device__ __forceinline__ void mbar_expect_tx(uint32_t m, uint32_t bytes) {
    asm volatile("mbarrier.arrive.expect_tx.shared.b64 _, [%0], %1;" :: "r"(m), "r"(bytes) : "memory");
}
__device__ __forceinline__ void mbar_arrive(uint32_t m) {
    asm volatile("mbarrier.arrive.shared.b64 _, [%0];" :: "r"(m) : "memory");
}
__device__ __forceinline__ void mbar_wait(uint32_t m, uint32_t parity) {
    asm volatile(
        "{\n\t.reg .pred P1;\n\t"
        "WAIT_%=:\n\t"
        "mbarrier.try_wait.parity.acquire.cta.shared::cta.b64 P1, [%0], %1, 0x989680;\n\t"
        "@P1 bra.uni DONE_%=;\n\t"
        "bra.uni WAIT_%=;\n\t"
        "DONE_%=:\n\t}" :: "r"(m), "r"(parity) : "memory");
}
__device__ __forceinline__ void bulk_g2s(uint32_t dst, const void* src, uint32_t bytes, uint32_t mbar) {
    asm volatile(
        "cp.async.bulk.shared::cta.global.mbarrier::complete_tx::bytes [%0], [%1], %2, [%3];"
        :: "r"(dst), "l"(src), "r"(bytes), "r"(mbar) : "memory");
}

__global__ void prep_W(const float* __restrict__ W) {
    int idx = blockIdx.x * blockDim.x + threadIdx.x;   // 8192
    int pr = idx >> 7, o = idx & 127;
    int r = ((pr >> 2) << 3) | (pr & 3);
    uint32_t pa = cvt2h(W[o * 256 + 2 * r + 1],       W[o * 256 + 2 * r]);
    uint32_t pb = cvt2h(W[o * 256 + 2 * (r + 4) + 1], W[o * 256 + 2 * (r + 4)]);
    g_W64[pr * WP + o] = ((u64)pb << 32) | pa;
}

// Producer (warp 0): stage chunk jj via cp.async.bulk.
__device__ __forceinline__ void produce(const float* __restrict__ x, char* smem,
                                        int jj, int sid, int lane,
                                        uint32_t xb, uint32_t mb) {
    const int s = jj % NSTAGE;
    const uint32_t full  = mb + (uint32_t)s * 8;
    const uint32_t empty = mb + 40 + (uint32_t)s * 8;
    if (jj >= NSTAGE) mbar_wait(empty, (uint32_t)(((jj - NSTAGE) / NSTAGE) & 1));

    const int tile = sid + (jj >> 3) * NSTR;
    const int b = tile & 7;
    const long p0 = (long)(tile >> 3) * 64;
    const int cb = (jj & 7) * 16;
    const uint32_t slot = xb + (uint32_t)s * CHUNK_B;

    long vf = (long)T_IN - p0;
    int vbytes = (vf >= 68) ? 272 : (vf > 0 ? (int)vf * 4 : 0);

    if (vbytes < 272) {
        char* slotp = smem + SM_X + (size_t)s * CHUNK_B;
        if (vbytes == 0) {
            for (int i = lane; i < CHUNK_B / 16; i += 32)
                *reinterpret_cast<uint4*>(slotp + i * 16) = make_uint4(0, 0, 0, 0);
        } else if (lane < 16) {
            for (int off = vbytes; off < 272; off += 16)
                *reinterpret_cast<uint4*>(slotp + lane * (XP * 4) + off) = make_uint4(0, 0, 0, 0);
        }
        __syncwarp();
    }
    if (lane == 0) {
        if (vbytes > 0) mbar_expect_tx(full, (uint32_t)(16 * vbytes));
        else            mbar_arrive(full);
    }
    __syncwarp();
    if (lane < 16 && vbytes > 0) {
        const float* src = x + ((size_t)b * CIN + (size_t)(cb + lane)) * T_IN + p0;
        bulk_g2s(slot + (uint32_t)lane * (XP * 4), src, (uint32_t)vbytes, full);
    }
}

__global__ __launch_bounds__(256, 3)
void dconv14(const float* __restrict__ x,
             const float* __restrict__ bias,
             float* __restrict__ out)
{
    extern __shared__ char smem[];
    float* sBias = reinterpret_cast<float*>(smem + SM_BIAS);

    const int tid = threadIdx.x;
    const int lane = tid & 31;
    const int t = lane & 3;
    const int g = lane >> 2;
    const int wid = tid >> 5;
    const int ob   = (wid & 3) * 32;    // M: 32 outputs per warp (4 M-groups)
    const int pgrp = wid >> 2;          // N: 32-position group (2 N-groups)

    const uint32_t sb = smem_u32(smem);
    const uint32_t xb = sb + SM_X;
    const uint32_t mb = sb + SM_MBAR;
    const float* sX = reinterpret_cast<const float*>(smem + SM_X);

    const int sid = blockIdx.x;
    const int nt  = (NTILE2 - 1 - sid) / NSTR + 1;
    const int nc  = nt * 8;

    if (tid < 128) sBias[tid] = bias[tid];
    if (tid == 0) {
        #pragma unroll
        for (int s = 0; s < NSTAGE; ++s) {
            mbar_init(mb + s * 8, 1);        // full: tx-based
            mbar_init(mb + 40 + s * 8, 8);   // empty: 8 warps
        }
    }
    __syncthreads();

    float acc[2][4][4];
    #pragma unroll
    for (int mf = 0; mf < 2; ++mf)
        #pragma unroll
        for (int nf = 0; nf < 4; ++nf)
            #pragma unroll
            for (int i = 0; i < 4; ++i) acc[mf][nf][i] = 0.0f;

    if (wid == 0) {
        #pragma unroll
        for (int j0 = 0; j0 < LOOKAHEAD; ++j0)
            if (j0 < nc) produce(x, smem, j0, sid, lane, xb, mb);
    }

    for (int j = 0; j < nc; ++j) {
        if (wid == 0 && j + LOOKAHEAD < nc)
            produce(x, smem, j + LOOKAHEAD, sid, lane, xb, mb);

        const int s = j % NSTAGE;
        mbar_wait(mb + (uint32_t)s * 8, (uint32_t)((j / NSTAGE) & 1));

        // ---- consume chunk j: 2 k-steps ----
        const float* Xc = sX + (size_t)s * (CHUNK_B / 4);
        #pragma unroll
        for (int kk = 0; kk < 2; ++kk) {
            const int klg = (j & 7) * 2 + kk;
            const float* xr = Xc + (size_t)(8 * kk + t) * XP + pgrp * 32 + g;
            uint32_t bf[8];
            #pragma unroll
            for (int nf = 0; nf < 4; ++nf) {
                float v0 = xr[8 * nf],          v2 = xr[8 * nf + 2];
                float w0 = xr[4 * XP + 8 * nf], w2 = xr[4 * XP + 8 * nf + 2];
                bf[2 * nf]     = cvt2h(v2, v0);
                bf[2 * nf + 1] = cvt2h(w2, w0);
            }
            // W from global, L1-resident
            const u64* wr = g_W64 + (size_t)(4 * klg + t) * WP;
            #pragma unroll
            for (int mf = 0; mf < 2; ++mf) {
                const int o = ob + 16 * mf + g;
                u64 wA = __ldg(wr + o);
                u64 wB = __ldg(wr + o + 8);
                uint32_t a[4] = { (uint32_t)wA, (uint32_t)wB,
                                  (uint32_t)(wA >> 32), (uint32_t)(wB >> 32) };
                #pragma unroll
                for (int nf = 0; nf < 4; ++nf)
                    mma16816h(acc[mf][nf], a, bf[2 * nf], bf[2 * nf + 1]);
            }
        }
        if (lane == 0) mbar_arrive(mb + 40 + (uint32_t)s * 8);   // empty (per warp)

        // ---- tile boundary: epilogue ----
        if ((j & 7) == 7) {
            const int tile = sid + (j >> 3) * NSTR;
            const int b = tile & 7;
            const long p0 = (long)(tile >> 3) * 64;
            #pragma unroll
            for (int mf = 0; mf < 2; ++mf) {
                const int o = ob + 16 * mf + g;
                const float b0 = sBias[o], b1 = sBias[o + 8];
                #pragma unroll
                for (int nf = 0; nf < 4; ++nf) {
                    long p = p0 + pgrp * 32 + 8 * nf + 2 * t;
                    float* r0 = out + ((size_t)b * OUTC + o) * P_OUT + p;
                    float* r1 = r0 + (size_t)8 * P_OUT;
                    if (p < P_OUT) {
                        r0[0] = acc[mf][nf][0] + b0;
                        r1[0] = acc[mf][nf][2] + b1;
                    }
                    if (p + 1 < P_OUT) {
                        r0[1] = acc[mf][nf][1] + b0;
                        r1[1] = acc[mf][nf][3] + b1;
                    }
                    #pragma unroll
                    for (int k = 0; k < 4; ++k) acc[mf][nf][k] = 0.0f;
                }
            }
        }
    }
}

extern "C" void kernel_launch(void* const* d_in, const int* in_sizes, int n_in,
                              void* d_out, int out_size)
{
    const float* x  = (const float*)d_in[0];   // (8, 128, 32768)
    const float* W  = (const float*)d_in[1];   // (128, 128, 2)
    const float* bs = (const float*)d_in[2];   // (128,)
    float* out = (float*)d_out;                // (8, 128, 32769)

    cudaFuncSetAttribute(dconv14, cudaFuncAttributeMaxDynamicSharedMemorySize, SM_TOT);

    prep_W<<<32, 256>>>(W);
    dconv14<<<GRID, 256, SM_TOT>>>(x, bs, out);
}

// round 15
// speedup vs baseline: 1.0944x; 1.0944x over previous
#include <cuda_runtime.h>
#include <cuda_fp16.h>
#include <cstdint>

#define CIN    128
#define OUTC   128
#define T_IN   32768
#define P_OUT  32769
#define NTILE2 4104          // 513 p-tiles(64 pos) * 8 batches = 456 * 9
#define TSTR   456           // tile-streams per output-half
#define GRID   456           // 228 CTA-pairs; 3 CTAs/SM

#define WPS 68               // u64 pitch of smem W-half rows (68 % 16 == 4, conflict-free LDS.64)
#define XP  72               // f32 pitch, x rows (bank = 8t+g, conflict-free; 288B)
#define NSTAGE 4
#define LOOKAHEAD 3
#define CHUNK_B   (16 * XP * 4)      // 4608 B (16 channels x 72 f32)
#define RING_B    (NSTAGE * CHUNK_B) // 18432 B per stream

// smem byte offsets (72320 B per CTA -> 3 CTAs/SM)
#define SM_W    0                    // u64 [64][WPS] = 34816
#define SM_X    34816                // 2 streams x 4 stages x 4608 = 36864
#define SM_BIAS 71680                // 256 (+pad)
#define SM_MBAR 72192                // 2 streams x (4 full + 4 empty) x 8 = 128
#define SM_TOT  72320

typedef unsigned long long u64;

// Full W image: [pr][o] u64 = { lo32: f16x2 pair(kr=r), hi32: f16x2 pair(kr=r+4) }
__device__ __align__(16) u64 g_W64[64 * 132];

__device__ __forceinline__ uint32_t smem_u32(const void* p) {
    uint32_t a;
    asm("{ .reg .u64 t; cvta.to.shared.u64 t, %1; cvt.u32.u64 %0, t; }" : "=r"(a) : "l"(p));
    return a;
}
__device__ __forceinline__ uint32_t cvt2h(float hi, float lo) {
    uint32_t r;
    asm("cvt.rn.f16x2.f32 %0, %1, %2;" : "=r"(r) : "f"(hi), "f"(lo));
    return r;
}
__device__ __forceinline__ void mma16816h(float* d, const uint32_t* a, uint32_t b0, uint32_t b1) {
    asm volatile(
        "mma.sync.aligned.m16n8k16.row.col.f32.f16.f16.f32 "
        "{%0,%1,%2,%3}, {%4,%5,%6,%7}, {%8,%9}, {%0,%1,%2,%3};"
        : "+f"(d[0]), "+f"(d[1]), "+f"(d[2]), "+f"(d[3])
        : "r"(a[0]), "r"(a[1]), "r"(a[2]), "r"(a[3]), "r"(b0), "r"(b1));
}
__device__ __forceinline__ void mbar_init(uint32_t m, uint32_t cnt) {
    asm volatile("mbarrier.init.shared.b64 [%0], %1;" :: "r"(m), "r"(cnt) : "memory");
}
__device__ __forceinline__ void mbar_expect_tx(uint32_t m, uint32_t bytes) {
    asm volatile("mbarrier.arrive.expect_tx.shared.b64 _, [%0], %1;" :: "r"(m), "r"(bytes) : "memory");
}
__device__ __forceinline__ void mbar_arrive(uint32_t m) {
    asm volatile("mbarrier.arrive.shared.b64 _, [%0];" :: "r"(m) : "memory");
}
__device__ __forceinline__ void mbar_wait(uint32_t m, uint32_t parity) {
    asm volatile(
        "{\n\t.reg .pred P1;\n\t"
        "WAIT_%=:\n\t"
        "mbarrier.try_wait.parity.acquire.cta.shared::cta.b64 P1, [%0], %1, 0x989680;\n\t"
        "@P1 bra.uni DONE_%=;\n\t"
        "bra.uni WAIT_%=;\n\t"
        "DONE_%=:\n\t}" :: "r"(m), "r"(parity) : "memory");
}
__device__ __forceinline__ void bulk_g2s(uint32_t dst, const void* src, uint32_t bytes, uint32_t mbar) {
    asm volatile(
        "cp.async.bulk.shared::cta.global.mbarrier::complete_tx::bytes [%0], [%1], %2, [%3];"
        :: "r"(dst), "l"(src), "r"(bytes), "r"(mbar) : "memory");
}

__global__ void prep_W(const float* __restrict__ W) {
    int idx = blockIdx.x * blockDim.x + threadIdx.x;   // 8192
    int pr = idx >> 7, o = idx & 127;
    int r = ((pr >> 2) << 3) | (pr & 3);
    uint32_t pa = cvt2h(W[o * 256 + 2 * r + 1],       W[o * 256 + 2 * r]);
    uint32_t pb = cvt2h(W[o * 256 + 2 * (r + 4) + 1], W[o * 256 + 2 * (r + 4)]);
    g_W64[pr * 132 + o] = ((u64)pb << 32) | pa;
}

// Producer (warp 0 of each stream): stage chunk jj via cp.async.bulk.
__device__ __forceinline__ void produce(const float* __restrict__ x, char* smem,
                                        int jj, int tsid, int lane,
                                        uint32_t xs, uint32_t mbs, int h) {
    const int s = jj & (NSTAGE - 1);
    const uint32_t full  = mbs + (uint32_t)s * 8;
    const uint32_t empty = mbs + 32 + (uint32_t)s * 8;
    if (jj >= NSTAGE) mbar_wait(empty, (uint32_t)(((jj - NSTAGE) >> 2) & 1));

    const int tile = tsid + (jj >> 3) * TSTR;
    const int b = tile & 7;
    const long p0 = (long)(tile >> 3) * 64;
    const int cb = (jj & 7) * 16;
    const uint32_t slot = xs + (uint32_t)s * CHUNK_B;

    long vf = (long)T_IN - p0;
    int vbytes = (vf >= 68) ? 272 : (vf > 0 ? (int)vf * 4 : 0);   // multiple of 16

    if (vbytes < 272) {
        char* slotp = smem + SM_X + (size_t)h * RING_B + (size_t)s * CHUNK_B;
        if (vbytes == 0) {
            for (int i = lane; i < CHUNK_B / 16; i += 32)
                *reinterpret_cast<uint4*>(slotp + i * 16) = make_uint4(0, 0, 0, 0);
        } else if (lane < 16) {
            for (int off = vbytes; off < 272; off += 16)
                *reinterpret_cast<uint4*>(slotp + lane * (XP * 4) + off) = make_uint4(0, 0, 0, 0);
        }
        __syncwarp();
    }
    if (lane == 0) {
        if (vbytes > 0) mbar_expect_tx(full, (uint32_t)(16 * vbytes));
        else            mbar_arrive(full);
    }
    __syncwarp();
    if (lane < 16 && vbytes > 0) {
        const float* src = x + ((size_t)b * CIN + (size_t)(cb + lane)) * T_IN + p0;
        bulk_g2s(slot + (uint32_t)lane * (XP * 4), src, (uint32_t)vbytes, full);
    }
}

__global__ __launch_bounds__(256, 3)
void dconv15(const float* __restrict__ x,
             const float* __restrict__ bias,
             float* __restrict__ out)
{
    extern __shared__ char smem[];
    u64*   sW    = reinterpret_cast<u64*>(smem + SM_W);
    float* sBias = reinterpret_cast<float*>(smem + SM_BIAS);

    const int tid = threadIdx.x;
    const int lane = tid & 31;
    const int t = lane & 3;
    const int g = lane >> 2;
    const int wid = tid >> 5;
    const int h    = wid >> 2;          // stream 0/1 within CTA
    const int widh = wid & 3;
    const int ob   = (widh & 1) * 32;   // local M base (0/32)
    const int pgrp = widh >> 1;         // 32-position group (0/1)

    const int bx = blockIdx.x;
    const int ohalf = bx & 1;           // outputs [64*ohalf, 64*ohalf+64)
    const int tsid = (bx >> 1) * 2 + h; // tile stream id in [0, 456)

    const uint32_t sb  = smem_u32(smem);
    const uint32_t xs  = sb + SM_X + (uint32_t)h * RING_B;
    const uint32_t mbs = sb + SM_MBAR + (uint32_t)h * 64;
    const float* sX = reinterpret_cast<const float*>(smem + SM_X) + (size_t)h * (RING_B / 4);

    const int nt = (NTILE2 - 1 - tsid) / TSTR + 1;   // = 9
    const int nc = nt * 8;

    // one-time: W-half image (re-pitched 132 -> 68, column offset 64*ohalf) + bias + mbars
    for (int i = tid; i < 64 * WPS; i += 256) {
        int pr = i / WPS, oo = i - pr * WPS;
        sW[i] = (oo < 64) ? g_W64[pr * 132 + 64 * ohalf + oo] : 0ull;
    }
    if (tid < 64) sBias[tid] = bias[64 * ohalf + tid];
    if (tid == 0) {
        #pragma unroll
        for (int hh = 0; hh < 2; ++hh)
            #pragma unroll
            for (int s = 0; s < NSTAGE; ++s) {
                mbar_init(sb + SM_MBAR + hh * 64 + s * 8, 1);        // full: tx-based
                mbar_init(sb + SM_MBAR + hh * 64 + 32 + s * 8, 4);   // empty: 4 warps
            }
    }
    __syncthreads();

    float acc[2][4][4];
    #pragma unroll
    for (int mf = 0; mf < 2; ++mf)
        #pragma unroll
        for (int nf = 0; nf < 4; ++nf)
            #pragma unroll
            for (int i = 0; i < 4; ++i) acc[mf][nf][i] = 0.0f;

    if (widh == 0) {
        #pragma unroll
        for (int j0 = 0; j0 < LOOKAHEAD; ++j0)
            if (j0 < nc) produce(x, smem, j0, tsid, lane, xs, mbs, h);
    }

    for (int j = 0; j < nc; ++j) {
        if (widh == 0 && j + LOOKAHEAD < nc)
            produce(x, smem, j + LOOKAHEAD, tsid, lane, xs, mbs, h);

        const int s = j & (NSTAGE - 1);
        mbar_wait(mbs + (uint32_t)s * 8, (uint32_t)((j >> 2) & 1));

        // ---- consume chunk j: 2 k-steps ----
        const float* Xc = sX + (size_t)s * (CHUNK_B / 4);
        #pragma unroll
        for (int kk = 0; kk < 2; ++kk) {
            const int klg = (j & 7) * 2 + kk;
            const float* xr = Xc + (size_t)(8 * kk + t) * XP + pgrp * 32 + g;
            uint32_t bf[8];
            #pragma unroll
            for (int nf = 0; nf < 4; ++nf) {
                float v0 = xr[8 * nf],          v2 = xr[8 * nf + 2];
                float w0 = xr[4 * XP + 8 * nf], w2 = xr[4 * XP + 8 * nf + 2];
                bf[2 * nf]     = cvt2h(v2, v0);
                bf[2 * nf + 1] = cvt2h(w2, w0);
            }
            const u64* wr = sW + (size_t)(4 * klg + t) * WPS;
            #pragma unroll
            for (int mf = 0; mf < 2; ++mf) {
                const int o = ob + 16 * mf + g;   // local output row
                u64 wA = wr[o], wB = wr[o + 8];
                uint32_t a[4] = { (uint32_t)wA, (uint32_t)wB,
                                  (uint32_t)(wA >> 32), (uint32_t)(wB >> 32) };
                #pragma unroll
                for (int nf = 0; nf < 4; ++nf)
                    mma16816h(acc[mf][nf], a, bf[2 * nf], bf[2 * nf + 1]);
            }
        }
        if (lane == 0) mbar_arrive(mbs + 32 + (uint32_t)s * 8);    // empty (per warp)

        // ---- tile boundary: epilogue ----
        if ((j & 7) == 7) {
            const int tile = tsid + (j >> 3) * TSTR;
            const int b = tile & 7;
            const long p0 = (long)(tile >> 3) * 64;
            #pragma unroll
            for (int mf = 0; mf < 2; ++mf) {
                const int ol = ob + 16 * mf + g;
                const int og = 64 * ohalf + ol;
                const float b0 = sBias[ol], b1 = sBias[ol + 8];
                #pragma unroll
                for (int nf = 0; nf < 4; ++nf) {
                    long p = p0 + pgrp * 32 + 8 * nf + 2 * t;
                    float* r0 = out + ((size_t)b * OUTC + og) * P_OUT + p;
                    float* r1 = r0 + (size_t)8 * P_OUT;
                    if (p < P_OUT) {
                        r0[0] = acc[mf][nf][0] + b0;
                        r1[0] = acc[mf][nf][2] + b1;
                    }
                    if (p + 1 < P_OUT) {
                        r0[1] = acc[mf][nf][1] + b0;
                        r1[1] = acc[mf][nf][3] + b1;
                    }
                    #pragma unroll
                    for (int k = 0; k < 4; ++k) acc[mf][nf][k] = 0.0f;
                }
            }
        }
    }
}

extern "C" void kernel_launch(void* const* d_in, const int* in_sizes, int n_in,
                              void* d_out, int out_size)
{
    const float* x  = (const float*)d_in[0];   // (8, 128, 32768)
    const float* W  = (const float*)d_in[1];   // (128, 128, 2)
    const float* bs = (const float*)d_in[2];   // (128,)
    float* out = (float*)d_out;                // (8, 128, 32769)

    cudaFuncSetAttribute(dconv15, cudaFuncAttributeMaxDynamicSharedMemorySize, SM_TOT);

    prep_W<<<32, 256>>>(W);
    dconv15<<<GRID, 256, SM_TOT>>>(x, bs, out);
}

// round 16
// speedup vs baseline: 1.2177x; 1.1127x over previous
#include <cuda_runtime.h>
#include <cuda_fp16.h>
#include <cstdint>

#define CIN    128
#define OUTC   128
#define T_IN   32768
#define P_OUT  32769
#define NTILE2 4104          // 513 p-tiles(64 pos) * 8 batches
#define NSTR   608           // 304 CTAs * 2 half-streams
#define GRID   304

#define WP 132               // u64 pitch, W pair rows (conflict-free LDS.64)
#define XP 72                // f32 pitch, x rows (bank = 8t+g, conflict-free; 288B)
#define NSTAGE 5
#define LOOKAHEAD 4
#define CHUNK_B   (16 * XP * 4)      // 4608 B per chunk (16 channels x 72 f32)
#define XHALF_B   (NSTAGE * CHUNK_B) // 23040 B per half

// smem byte offsets (114336 B per CTA -> 2 CTAs/SM)
#define SM_W    0                      // u64 [64][WP] = 67584
#define SM_X    67584                  // 2 halves x 5 stages x 4608 = 46080
#define SM_BIAS 113664                 // 512
#define SM_MBAR 114176                 // 2 halves x (5 full + 5 empty) x 8B = 160
#define SM_TOT  114336

typedef unsigned long long u64;

__device__ __align__(16) u64 g_W64[64 * WP];

__device__ __forceinline__ uint32_t smem_u32(const void* p) {
    uint32_t a;
    asm("{ .reg .u64 t; cvta.to.shared.u64 t, %1; cvt.u32.u64 %0, t; }" : "=r"(a) : "l"(p));
    return a;
}
__device__ __forceinline__ uint32_t cvt2h(float hi, float lo) {
    uint32_t r;
    asm("cvt.rn.f16x2.f32 %0, %1, %2;" : "=r"(r) : "f"(hi), "f"(lo));
    return r;
}
__device__ __forceinline__ void mma16816h(float* d, const uint32_t* a, uint32_t b0, uint32_t b1) {
    asm volatile(
        "mma.sync.aligned.m16n8k16.row.col.f32.f16.f16.f32 "
        "{%0,%1,%2,%3}, {%4,%5,%6,%7}, {%8,%9}, {%0,%1,%2,%3};"
        : "+f"(d[0]), "+f"(d[1]), "+f"(d[2]), "+f"(d[3])
        : "r"(a[0]), "r"(a[1]), "r"(a[2]), "r"(a[3]), "r"(b0), "r"(b1));
}
__device__ __forceinline__ void mbar_init(uint32_t m, uint32_t cnt) {
    asm volatile("mbarrier.init.shared.b64 [%0], %1;" :: "r"(m), "r"(cnt) : "memory");
}
__device__ __forceinline__ void mbar_expect_tx(uint32_t m, uint32_t bytes) {
    asm volatile("mbarrier.arrive.expect_tx.shared.b64 _, [%0], %1;" :: "r"(m), "r"(bytes) : "memory");
}
__device__ __forceinline__ void mbar_arrive(uint32_t m) {
    asm volatile("mbarrier.arrive.shared.b64 _, [%0];" :: "r"(m) : "memory");
}
__device__ __forceinline__ void mbar_wait(uint32_t m, uint32_t parity) {
    asm volatile(
        "{\n\t.reg .pred P1;\n\t"
        "WAIT_%=:\n\t"
        "mbarrier.try_wait.parity.acquire.cta.shared::cta.b64 P1, [%0], %1, 0x989680;\n\t"
        "@P1 bra.uni DONE_%=;\n\t"
        "bra.uni WAIT_%=;\n\t"
        "DONE_%=:\n\t}" :: "r"(m), "r"(parity) : "memory");
}
__device__ __forceinline__ void bulk_g2s(uint32_t dst, const void* src, uint32_t bytes, uint32_t mbar) {
    asm volatile(
        "cp.async.bulk.shared::cta.global.mbarrier::complete_tx::bytes [%0], [%1], %2, [%3];"
        :: "r"(dst), "l"(src), "r"(bytes), "r"(mbar) : "memory");
}

__global__ void prep_W(const float* __restrict__ W) {
    int idx = blockIdx.x * blockDim.x + threadIdx.x;   // 8192
    int pr = idx >> 7, o = idx & 127;
    int r = ((pr >> 2) << 3) | (pr & 3);
    uint32_t pa = cvt2h(W[o * 256 + 2 * r + 1],       W[o * 256 + 2 * r]);
    uint32_t pb = cvt2h(W[o * 256 + 2 * (r + 4) + 1], W[o * 256 + 2 * (r + 4)]);
    g_W64[pr * WP + o] = ((u64)pb << 32) | pa;
}

// Producer (warp 0 of each half): stage chunk jj via cp.async.bulk.
__device__ __forceinline__ void produce(const float* __restrict__ x, char* smem,
                                        int jj, int sid, int lane,
                                        uint32_t xbh, uint32_t mbh, int half) {
    const int s = jj % NSTAGE;
    const uint32_t full  = mbh + (uint32_t)s * 8;
    const uint32_t empty = mbh + 40 + (uint32_t)s * 8;
    if (jj >= NSTAGE) mbar_wait(empty, (uint32_t)(((jj - NSTAGE) / NSTAGE) & 1));

    const int tile = sid + (jj >> 3) * NSTR;
    const int b = tile & 7;
    const long p0 = (long)(tile >> 3) * 64;
    const int cb = (jj & 7) * 16;
    const uint32_t slot = xbh + (uint32_t)s * CHUNK_B;

    long vf = (long)T_IN - p0;
    int vbytes = (vf >= 68) ? 272 : (vf > 0 ? (int)vf * 4 : 0);

    if (vbytes < 272) {
        char* slotp = smem + SM_X + (size_t)half * XHALF_B + (size_t)s * CHUNK_B;
        if (vbytes == 0) {
            for (int i = lane; i < CHUNK_B / 16; i += 32)
                *reinterpret_cast<uint4*>(slotp + i * 16) = make_uint4(0, 0, 0, 0);
        } else if (lane < 16) {
            for (int off = vbytes; off < 272; off += 16)
                *reinterpret_cast<uint4*>(slotp + lane * (XP * 4) + off) = make_uint4(0, 0, 0, 0);
        }
        __syncwarp();
    }
    if (lane == 0) {
        if (vbytes > 0) mbar_expect_tx(full, (uint32_t)(16 * vbytes));
        else            mbar_arrive(full);
    }
    __syncwarp();
    if (lane < 16 && vbytes > 0) {
        const float* src = x + ((size_t)b * CIN + (size_t)(cb + lane)) * T_IN + p0;
        bulk_g2s(slot + (uint32_t)lane * (XP * 4), src, (uint32_t)vbytes, full);
    }
}

// Build one k-step's B fragments from staged f32 (8 LDS pairs + 8 cvt).
__device__ __forceinline__ void build_frags(const float* __restrict__ Xc, int kk,
                                            int t, int pgrp, int g, uint32_t* bf) {
    const float* xr = Xc + (size_t)(8 * kk + t) * XP + pgrp * 32 + g;
    #pragma unroll
    for (int nf = 0; nf < 4; ++nf) {
        float v0 = xr[8 * nf],          v2 = xr[8 * nf + 2];
        float w0 = xr[4 * XP + 8 * nf], w2 = xr[4 * XP + 8 * nf + 2];
        bf[2 * nf]     = cvt2h(v2, v0);
        bf[2 * nf + 1] = cvt2h(w2, w0);
    }
}

__global__ __launch_bounds__(256, 2)
void dconv16(const float* __restrict__ x,
             const float* __restrict__ bias,
             float* __restrict__ out)
{
    extern __shared__ char smem[];
    u64*   sW    = reinterpret_cast<u64*>(smem + SM_W);
    float* sBias = reinterpret_cast<float*>(smem + SM_BIAS);

    const int tid = threadIdx.x;
    const int lane = tid & 31;
    const int t = lane & 3;
    const int g = lane >> 2;
    const int wid = tid >> 5;
    const int h    = wid >> 2;          // half-stream 0/1
    const int widh = wid & 3;
    const int ob   = (widh >> 1) * 64;  // M: output base
    const int pgrp = widh & 1;          // N: 32-position group

    const uint32_t sb  = smem_u32(smem);
    const uint32_t xbh = sb + SM_X + (uint32_t)h * XHALF_B;
    const uint32_t mbh = sb + SM_MBAR + (uint32_t)h * 80;
    const float* sXh = reinterpret_cast<const float*>(smem + SM_X) + (size_t)h * (XHALF_B / 4);

    const int sid = blockIdx.x * 2 + h;
    const int nt  = (NTILE2 - 1 - sid) / NSTR + 1;
    const int nc  = nt * 8;

    // one-time: W image + bias + mbarrier init
    {
        const uint4* src = reinterpret_cast<const uint4*>(g_W64);
        uint4* dst = reinterpret_cast<uint4*>(sW);
        #pragma unroll 4
        for (int i = tid; i < 4224; i += 256) dst[i] = src[i];
    }
    if (tid < 128) sBias[tid] = bias[tid];
    if (tid == 0) {
        #pragma unroll
        for (int hh = 0; hh < 2; ++hh)
            #pragma unroll
            for (int s = 0; s < NSTAGE; ++s) {
                mbar_init(sb + SM_MBAR + hh * 80 + s * 8, 1);        // full: tx-based
                mbar_init(sb + SM_MBAR + hh * 80 + 40 + s * 8, 4);   // empty: 4 warps
            }
    }
    __syncthreads();

    float acc[4][4][4];
    #pragma unroll
    for (int mf = 0; mf < 4; ++mf)
        #pragma unroll
        for (int nf = 0; nf < 4; ++nf)
            #pragma unroll
            for (int i = 0; i < 4; ++i) acc[mf][nf][i] = 0.0f;

    // prologue: producer stages first LOOKAHEAD chunks
    if (widh == 0) {
        #pragma unroll
        for (int j0 = 0; j0 < LOOKAHEAD; ++j0)
            if (j0 < nc) produce(x, smem, j0, sid, lane, xbh, mbh, h);
    }

    // pre-wait chunk 0, prefetch its kk0 frags
    uint32_t bfA[8], bfB[8];
    mbar_wait(mbh, 0u);
    build_frags(sXh, 0, t, pgrp, g, bfA);

    int j = 0;
    for (int tt = 0; tt < nt; ++tt) {
        #pragma unroll 1
        for (int c = 0; c < 8; ++c, ++j) {
            if (widh == 0 && j + LOOKAHEAD < nc)
                produce(x, smem, j + LOOKAHEAD, sid, lane, xbh, mbh, h);

            const int s = j % NSTAGE;
            const float* Xc = sXh + (size_t)s * (CHUNK_B / 4);

            // build kk1 frags (LDS overlaps with kk0 HMMAs below)
            build_frags(Xc, 1, t, pgrp, g, bfB);

            // HMMA kk0 from registers
            {
                const int klg = (j & 7) * 2;
                const u64* wr = sW + (size_t)(4 * klg + t) * WP;
                #pragma unroll
                for (int mf = 0; mf < 4; ++mf) {
                    const int o = ob + 16 * mf + g;
                    u64 wA = wr[o], wB = wr[o + 8];
                    uint32_t a[4] = { (uint32_t)wA, (uint32_t)wB,
                                      (uint32_t)(wA >> 32), (uint32_t)(wB >> 32) };
                    #pragma unroll
                    for (int nf = 0; nf < 4; ++nf)
                        mma16816h(acc[mf][nf], a, bfA[2 * nf], bfA[2 * nf + 1]);
                }
            }

            // wait next chunk, prefetch its kk0 frags (LDS overlaps kk1 HMMAs below)
            if (j + 1 < nc) {
                const int sn = (j + 1) % NSTAGE;
                mbar_wait(mbh + (uint32_t)sn * 8, (uint32_t)(((j + 1) / NSTAGE) & 1));
                build_frags(sXh + (size_t)sn * (CHUNK_B / 4), 0, t, pgrp, g, bfA);
            }

            // HMMA kk1 from registers
            {
                const int klg = (j & 7) * 2 + 1;
                const u64* wr = sW + (size_t)(4 * klg + t) * WP;
                #pragma unroll
                for (int mf = 0; mf < 4; ++mf) {
                    const int o = ob + 16 * mf + g;
                    u64 wA = wr[o], wB = wr[o + 8];
                    uint32_t a[4] = { (uint32_t)wA, (uint32_t)wB,
                                      (uint32_t)(wA >> 32), (uint32_t)(wB >> 32) };
                    #pragma unroll
                    for (int nf = 0; nf < 4; ++nf)
                        mma16816h(acc[mf][nf], a, bfB[2 * nf], bfB[2 * nf + 1]);
                }
            }

            if (lane == 0) mbar_arrive(mbh + 40 + (uint32_t)s * 8);   // empty (per warp)
        }

        // ---- tile boundary: epilogue ----
        {
            const int tile = sid + (tt) * NSTR;
            const int b = tile & 7;
            const long p0 = (long)(tile >> 3) * 64;
            #pragma unroll
            for (int mf = 0; mf < 4; ++mf) {
                const int o = ob + 16 * mf + g;
                const float b0 = sBias[o], b1 = sBias[o + 8];
                #pragma unroll
                for (int nf = 0; nf < 4; ++nf) {
                    long p = p0 + pgrp * 32 + 8 * nf + 2 * t;
                    float* r0 = out + ((size_t)b * OUTC + o) * P_OUT + p;
                    float* r1 = r0 + (size_t)8 * P_OUT;
                    if (p < P_OUT) {
                        r0[0] = acc[mf][nf][0] + b0;
                        r1[0] = acc[mf][nf][2] + b1;
                    }
                    if (p + 1 < P_OUT) {
                        r0[1] = acc[mf][nf][1] + b0;
                        r1[1] = acc[mf][nf][3] + b1;
                    }
                    #pragma unroll
                    for (int k = 0; k < 4; ++k) acc[mf][nf][k] = 0.0f;
                }
            }
        }
    }
}

extern "C" void kernel_launch(void* const* d_in, const int* in_sizes, int n_in,
                              void* d_out, int out_size)
{
    const float* x  = (const float*)d_in[0];   // (8, 128, 32768)
    const float* W  = (const float*)d_in[1];   // (128, 128, 2)
    const float* bs = (const float*)d_in[2];   // (128,)
    float* out = (float*)d_out;                // (8, 128, 32769)

    cudaFuncSetAttribute(dconv16, cudaFuncAttributeMaxDynamicSharedMemorySize, SM_TOT);

    prep_W<<<32, 256>>>(W);
    dconv16<<<GRID, 256, SM_TOT>>>(x, bs, out);
}